// round 9
// baseline (speedup 1.0000x reference)
#include <cuda_runtime.h>

// Shapes fixed by the problem: bz=4, C=32, H=W=256, NF=12 focal slices.
#define NF    12
#define BZ    4
#define C_    32
#define HW    65536           // 256*256
#define CHW   (C_ * HW)       // 2,097,152
#define CHW4  (CHW / 4)       // 524,288 = 2^19
#define HW4   (HW / 4)        // 16,384

#define BPB   74              // 74*4 = 296 blocks = exactly 2 per SM (one wave)
#define TPB   256
#define CLEN  7084            // base chunk; first 72 blocks get +1 (74*7084+72 = CHW4)

// Scratch (no allocation allowed).
__device__ float g_part[BZ * NF * BPB];

// ---------------------------------------------------------------------------
// Kernel 1: each block owns one (b, chunk) and accumulates ALL 12 focal MAEs
// (14 independent 16B loads in flight per iteration). Same hot-loop body as
// the best-measured R2 kernel; grid sized for a single perfectly-balanced wave.
// grid = (BPB, BZ).
// ---------------------------------------------------------------------------
__global__ __launch_bounds__(TPB, 2) void k_reduce(const float* __restrict__ x,
                                                   const float* __restrict__ xf,
                                                   const float* __restrict__ sal) {
    const int b  = blockIdx.y;
    const int bx = blockIdx.x;
    const int start = bx * CLEN + (bx < 72 ? bx : 72);
    const int end   = start + CLEN + (bx < 72 ? 1 : 0);

    const float4* __restrict__ xp = (const float4*)(x   + (size_t)b * CHW);
    const float4* __restrict__ sp = (const float4*)(sal + (size_t)b * HW);

    const float4* __restrict__ fp[NF];
#pragma unroll
    for (int f = 0; f < NF; ++f)
        fp[f] = (const float4*)(xf + ((size_t)f * BZ + b) * CHW);

    float acc[NF];
#pragma unroll
    for (int f = 0; f < NF; ++f) acc[f] = 0.f;

    for (int i = start + threadIdx.x; i < end; i += TPB) {
        const float4 a = xp[i];
        const float4 s = sp[i & (HW4 - 1)];       // sal broadcast over channels
        float4 g[NF];
#pragma unroll
        for (int f = 0; f < NF; ++f) g[f] = __ldcs(&fp[f][i]);
#pragma unroll
        for (int f = 0; f < NF; ++f) {
            acc[f] += fabsf(s.x * (a.x - g[f].x));
            acc[f] += fabsf(s.y * (a.y - g[f].y));
            acc[f] += fabsf(s.z * (a.z - g[f].z));
            acc[f] += fabsf(s.w * (a.w - g[f].w));
        }
    }

    // Warp shuffle reduce each of the 12 accumulators, then combine warps.
    const int lane = threadIdx.x & 31;
    const int warp = threadIdx.x >> 5;
#pragma unroll
    for (int f = 0; f < NF; ++f) {
        float v = acc[f];
#pragma unroll
        for (int o = 16; o > 0; o >>= 1)
            v += __shfl_down_sync(0xffffffffu, v, o);
        acc[f] = v;   // valid on lane 0
    }

    __shared__ float sh[TPB / 32][NF];
    if (lane == 0) {
#pragma unroll
        for (int f = 0; f < NF; ++f) sh[warp][f] = acc[f];
    }
    __syncthreads();
    if (threadIdx.x < NF) {
        const int f = threadIdx.x;
        float s = 0.f;
#pragma unroll
        for (int w = 0; w < TPB / 32; ++w) s += sh[w][f];
        g_part[(b * NF + f) * BPB + bx] = s;
    }
}

// ---------------------------------------------------------------------------
// Kernel 2: gather-copy with REDUNDANT per-block selection (no k_select, no
// atomics, no flags). Every block deterministically recomputes its batch's
// 12 MAEs from g_part (fixed summation order -> identical doubles in every
// block -> identical selection), picks the pair, then streams its chunk.
// Block chunk = 2048 float4, divides CHW4 -> one output row per block.
// ---------------------------------------------------------------------------
#define CPT 8
__global__ __launch_bounds__(TPB) void k_copy(const float* __restrict__ xf,
                                              float* __restrict__ out) {
    const long long q0 = (long long)blockIdx.x * (TPB * CPT);
    const int r     = (int)(q0 >> 19);      // output row 0..7, constant per block
    const int b     = r & (BZ - 1);
    const int which = r >> 2;

    // ---- selection preamble (identical in all blocks sharing batch b) ----
    __shared__ double mae[NF];
    __shared__ int sel2[2];
    if (threadIdx.x < NF) {
        double s = 0.0;
#pragma unroll 2
        for (int c = 0; c < BPB; ++c)
            s += (double)__ldg(&g_part[(b * NF + threadIdx.x) * BPB + c]);
        mae[threadIdx.x] = s;
    }
    __syncthreads();
    if (threadIdx.x == 0) {
        double best = -1.0;
        int bi = 0, bj = 0;
        for (int i = 0; i < NF; ++i)
            for (int j = i + 1; j < NF; ++j) {
                const double d = mae[i] - mae[j];
                const double v = d * d;          // 0.5 factor irrelevant for order
                if (v > best) { best = v; bi = i; bj = j; }
            }
        if (!(best > 0.0)) { bi = 0; bj = 0; }
        sel2[0] = bi;
        sel2[1] = bj;
    }
    __syncthreads();
    const int f = sel2[which];

    // ---- streaming copy: batch 8 loads, then 8 stores ----
    const float4* __restrict__ src = (const float4*)(xf + ((size_t)f * BZ + b) * CHW);
    float4* __restrict__ dst = (float4*)out;

    const int n0 = (int)(q0 & (CHW4 - 1)) + threadIdx.x;
    float4 v[CPT];
#pragma unroll
    for (int c = 0; c < CPT; ++c) v[c] = __ldcs(&src[n0 + c * TPB]);
#pragma unroll
    for (int c = 0; c < CPT; ++c) dst[q0 + threadIdx.x + c * TPB] = v[c];
}

// ---------------------------------------------------------------------------
extern "C" void kernel_launch(void* const* d_in, const int* in_sizes, int n_in,
                              void* d_out, int out_size) {
    const float* x   = (const float*)d_in[0];   // [4,32,256,256]
    const float* xf  = (const float*)d_in[1];   // [48,32,256,256]
    const float* sal = (const float*)d_in[2];   // [4,1,256,256]
    float*       out = (float*)d_out;           // [8,32,256,256]

    dim3 gridR(BPB, BZ);
    k_reduce<<<gridR, TPB>>>(x, xf, sal);
    const unsigned blocksC = (unsigned)((2LL * BZ * CHW4) / (TPB * CPT)); // 2048
    k_copy<<<blocksC, TPB>>>(xf, out);
}

// round 10
// speedup vs baseline: 1.1350x; 1.1350x over previous
#include <cuda_runtime.h>

// Shapes fixed by the problem: bz=4, C=32, H=W=256, NF=12 focal slices.
#define NF    12
#define BZ    4
#define C_    32
#define HW    65536           // 256*256
#define CHW   (C_ * HW)       // 2,097,152
#define CHW4  (CHW / 4)       // 524,288 = 2^19
#define HW4   (HW / 4)        // 16,384

#define BPB   128             // reduction blocks along the chunk axis (R2-exact)
#define TPB   256
#define CHUNK (CHW4 / BPB)    // 4096 float4 per block (16 iters/thread)

// Scratch (no allocation allowed).
__device__ float g_part[BZ * NF * BPB];   // 24 KB -> L2-resident for k_copy

// ---------------------------------------------------------------------------
// Kernel 1: EXACT R2 reduce (best measured: 68.7us @ 81% DRAM).
// Each block owns one (b, chunk) and accumulates ALL 12 focal MAEs
// (14 independent 16B loads in flight per iteration). grid = (BPB, BZ).
// ---------------------------------------------------------------------------
__global__ __launch_bounds__(TPB, 2) void k_reduce(const float* __restrict__ x,
                                                   const float* __restrict__ xf,
                                                   const float* __restrict__ sal) {
    const int b    = blockIdx.y;
    const int base = blockIdx.x * CHUNK;

    const float4* __restrict__ xp = (const float4*)(x   + (size_t)b * CHW);
    const float4* __restrict__ sp = (const float4*)(sal + (size_t)b * HW);

    const float4* __restrict__ fp[NF];
#pragma unroll
    for (int f = 0; f < NF; ++f)
        fp[f] = (const float4*)(xf + ((size_t)f * BZ + b) * CHW);

    float acc[NF];
#pragma unroll
    for (int f = 0; f < NF; ++f) acc[f] = 0.f;

    for (int i = threadIdx.x; i < CHUNK; i += TPB) {
        const int v = base + i;
        const float4 a = xp[v];
        const float4 s = sp[v & (HW4 - 1)];       // sal broadcast over channels
        float4 g[NF];
#pragma unroll
        for (int f = 0; f < NF; ++f) g[f] = __ldcs(&fp[f][v]);
#pragma unroll
        for (int f = 0; f < NF; ++f) {
            acc[f] += fabsf(s.x * (a.x - g[f].x));
            acc[f] += fabsf(s.y * (a.y - g[f].y));
            acc[f] += fabsf(s.z * (a.z - g[f].z));
            acc[f] += fabsf(s.w * (a.w - g[f].w));
        }
    }

    // Warp shuffle reduce each of the 12 accumulators, then combine warps.
    const int lane = threadIdx.x & 31;
    const int warp = threadIdx.x >> 5;
#pragma unroll
    for (int f = 0; f < NF; ++f) {
        float v = acc[f];
#pragma unroll
        for (int o = 16; o > 0; o >>= 1)
            v += __shfl_down_sync(0xffffffffu, v, o);
        acc[f] = v;   // valid on lane 0
    }

    __shared__ float sh[TPB / 32][NF];
    if (lane == 0) {
#pragma unroll
        for (int f = 0; f < NF; ++f) sh[warp][f] = acc[f];
    }
    __syncthreads();
    if (threadIdx.x < NF) {
        const int f = threadIdx.x;
        float s = 0.f;
#pragma unroll
        for (int w = 0; w < TPB / 32; ++w) s += sh[w][f];
        g_part[(b * NF + f) * BPB + blockIdx.x] = s;
    }
}

// ---------------------------------------------------------------------------
// Kernel 2: gather-copy with PARALLEL redundant selection preamble.
// 192 threads = 12 focals x 16 threads; each thread issues 8 INDEPENDENT L2
// loads (g_part is 24KB, L2-resident), then a fixed-order combine -> every
// block computes bit-identical doubles -> identical (i,j). ~1-2us, overlapped.
// Then streams its 2048-float4 chunk (one output row per block).
// ---------------------------------------------------------------------------
#define CPT 8
__global__ __launch_bounds__(TPB) void k_copy(const float* __restrict__ xf,
                                              float* __restrict__ out) {
    const long long q0 = (long long)blockIdx.x * (TPB * CPT);
    const int r     = (int)(q0 >> 19);      // output row 0..7, constant per block
    const int b     = r & (BZ - 1);
    const int which = r >> 2;
    const int t     = threadIdx.x;

    // ---- parallel deterministic selection preamble ----
    __shared__ double sp16[NF][16];
    __shared__ double mae[NF];
    __shared__ int sel2[2];
    if (t < NF * 16) {
        const int f = t >> 4;
        const int k = t & 15;
        const float* __restrict__ row = &g_part[(b * NF + f) * BPB + k * 8];
        double s = 0.0;
#pragma unroll
        for (int q = 0; q < 8; ++q)          // 8 independent L2 loads
            s += (double)__ldg(&row[q]);
        sp16[f][k] = s;
    }
    __syncthreads();
    if (t < NF) {
        double s = 0.0;
#pragma unroll
        for (int k = 0; k < 16; ++k) s += sp16[t][k];   // fixed order
        mae[t] = s;
    }
    __syncthreads();
    if (t == 0) {
        double best = -1.0;
        int bi = 0, bj = 0;
        for (int i = 0; i < NF; ++i)
            for (int j = i + 1; j < NF; ++j) {
                const double d = mae[i] - mae[j];
                const double v = d * d;      // 0.5 factor irrelevant for order
                if (v > best) { best = v; bi = i; bj = j; }
            }
        if (!(best > 0.0)) { bi = 0; bj = 0; }
        sel2[0] = bi;
        sel2[1] = bj;
    }
    __syncthreads();
    const int f = sel2[which];

    // ---- streaming copy: batch 8 loads, then 8 stores (R6-proven) ----
    const float4* __restrict__ src = (const float4*)(xf + ((size_t)f * BZ + b) * CHW);
    float4* __restrict__ dst = (float4*)out;

    const int n0 = (int)(q0 & (CHW4 - 1)) + t;
    float4 v[CPT];
#pragma unroll
    for (int c = 0; c < CPT; ++c) v[c] = __ldcs(&src[n0 + c * TPB]);
#pragma unroll
    for (int c = 0; c < CPT; ++c) dst[q0 + t + c * TPB] = v[c];
}

// ---------------------------------------------------------------------------
extern "C" void kernel_launch(void* const* d_in, const int* in_sizes, int n_in,
                              void* d_out, int out_size) {
    const float* x   = (const float*)d_in[0];   // [4,32,256,256]
    const float* xf  = (const float*)d_in[1];   // [48,32,256,256]
    const float* sal = (const float*)d_in[2];   // [4,1,256,256]
    float*       out = (float*)d_out;           // [8,32,256,256]

    dim3 gridR(BPB, BZ);
    k_reduce<<<gridR, TPB>>>(x, xf, sal);
    const unsigned blocksC = (unsigned)((2LL * BZ * CHW4) / (TPB * CPT)); // 2048
    k_copy<<<blocksC, TPB>>>(xf, out);
}

// round 11
// speedup vs baseline: 1.3043x; 1.1492x over previous
#include <cuda_runtime.h>

// Shapes fixed by the problem: bz=4, C=32, H=W=256, NF=12 focal slices.
#define NF    12
#define BZ    4
#define C_    32
#define HW    65536           // 256*256
#define CHW   (C_ * HW)       // 2,097,152
#define CHW4  (CHW / 4)       // 524,288 = 2^19
#define HW4   (HW / 4)        // 16,384

#define BPB   185             // 185*4 = 740 blocks = one full wave at 5 blocks/SM
#define RTPB  128             // reduce threads per block (occupancy: 5 blocks/SM)
#define CLEN  2833            // base chunk; first 183 chunks get +1 (185*2833+183 = CHW4)

// Scratch (no allocation allowed).
__device__ float g_part[BZ * NF * BPB];
__device__ int   g_sel[2 * BZ];   // [0..BZ) = i per batch, [BZ..2BZ) = j per batch

// ---------------------------------------------------------------------------
// Kernel 1: reduce. Body identical to the proven R2 kernel; only TPB (128)
// and grid shape changed to lift occupancy from 16 to 20 warps/SM.
// grid = (BPB, BZ).
// ---------------------------------------------------------------------------
__global__ __launch_bounds__(RTPB, 5) void k_reduce(const float* __restrict__ x,
                                                    const float* __restrict__ xf,
                                                    const float* __restrict__ sal) {
    const int b  = blockIdx.y;
    const int c  = blockIdx.x;
    const int start = c * CLEN + (c < 183 ? c : 183);
    const int end   = start + CLEN + (c < 183 ? 1 : 0);

    const float4* __restrict__ xp = (const float4*)(x   + (size_t)b * CHW);
    const float4* __restrict__ sp = (const float4*)(sal + (size_t)b * HW);

    const float4* __restrict__ fp[NF];
#pragma unroll
    for (int f = 0; f < NF; ++f)
        fp[f] = (const float4*)(xf + ((size_t)f * BZ + b) * CHW);

    float acc[NF];
#pragma unroll
    for (int f = 0; f < NF; ++f) acc[f] = 0.f;

    for (int i = start + threadIdx.x; i < end; i += RTPB) {
        const float4 a = xp[i];
        const float4 s = sp[i & (HW4 - 1)];       // sal broadcast over channels
        float4 g[NF];
#pragma unroll
        for (int f = 0; f < NF; ++f) g[f] = __ldcs(&fp[f][i]);
#pragma unroll
        for (int f = 0; f < NF; ++f) {
            acc[f] += fabsf(s.x * (a.x - g[f].x));
            acc[f] += fabsf(s.y * (a.y - g[f].y));
            acc[f] += fabsf(s.z * (a.z - g[f].z));
            acc[f] += fabsf(s.w * (a.w - g[f].w));
        }
    }

    // Warp shuffle reduce each of the 12 accumulators, then combine warps.
    const int lane = threadIdx.x & 31;
    const int warp = threadIdx.x >> 5;
#pragma unroll
    for (int f = 0; f < NF; ++f) {
        float v = acc[f];
#pragma unroll
        for (int o = 16; o > 0; o >>= 1)
            v += __shfl_down_sync(0xffffffffu, v, o);
        acc[f] = v;   // valid on lane 0
    }

    __shared__ float sh[RTPB / 32][NF];
    if (lane == 0) {
#pragma unroll
        for (int f = 0; f < NF; ++f) sh[warp][f] = acc[f];
    }
    __syncthreads();
    if (threadIdx.x < NF) {
        const int f = threadIdx.x;
        float s = 0.f;
#pragma unroll
        for (int w = 0; w < RTPB / 32; ++w) s += sh[w][f];
        g_part[(b * NF + f) * BPB + c] = s;
    }
}

// ---------------------------------------------------------------------------
// Kernel 2: tiny selection kernel. 192 threads = 4 partial-summers per (b,f),
// fixed-order double combine (deterministic), then per-batch pair argmax.
// ---------------------------------------------------------------------------
__global__ void k_select() {
    __shared__ double part4[BZ * NF][4];
    __shared__ double mae[BZ * NF];
    const int t = threadIdx.x;

    if (t < BZ * NF * 4) {
        const int bf = t >> 2;
        const int g  = t & 3;
        const int lo = g * 46;                       // 185 = 3*46 + 47
        const int hi = (g == 3) ? BPB : lo + 46;
        double s = 0.0;
        for (int q = lo; q < hi; ++q)
            s += (double)__ldg(&g_part[bf * BPB + q]);
        part4[bf][g] = s;
    }
    __syncthreads();
    if (t < BZ * NF)
        mae[t] = ((part4[t][0] + part4[t][1]) + part4[t][2]) + part4[t][3];
    __syncthreads();
    if (t < BZ) {
        double best = -1.0;
        int bi = 0, bj = 0;
        for (int i = 0; i < NF; ++i)
            for (int j = i + 1; j < NF; ++j) {
                const double d = mae[t * NF + i] - mae[t * NF + j];
                const double v = d * d;              // 0.5 irrelevant for ordering
                if (v > best) { best = v; bi = i; bj = j; }
            }
        if (!(best > 0.0)) { bi = 0; bj = 0; }
        g_sel[t]      = bi;
        g_sel[BZ + t] = bj;
    }
}

// ---------------------------------------------------------------------------
// Kernel 3: gather-copy (R6-proven, 18.6us). Batch 8 streaming loads into
// registers, then 8 write-back stores. Block chunk = 2048 float4.
// ---------------------------------------------------------------------------
#define TPB 256
#define CPT 8
__global__ __launch_bounds__(TPB) void k_copy(const float* __restrict__ xf,
                                              float* __restrict__ out) {
    const long long q0 = (long long)blockIdx.x * (TPB * CPT);
    const int r     = (int)(q0 >> 19);      // output row 0..7, constant per block
    const int b     = r & (BZ - 1);
    const int which = r >> 2;
    const int f     = g_sel[which * BZ + b];

    const float4* __restrict__ src = (const float4*)(xf + ((size_t)f * BZ + b) * CHW);
    float4* __restrict__ dst = (float4*)out;

    const int n0 = (int)(q0 & (CHW4 - 1)) + threadIdx.x;
    float4 v[CPT];
#pragma unroll
    for (int c = 0; c < CPT; ++c) v[c] = __ldcs(&src[n0 + c * TPB]);
#pragma unroll
    for (int c = 0; c < CPT; ++c) dst[q0 + threadIdx.x + c * TPB] = v[c];
}

// ---------------------------------------------------------------------------
extern "C" void kernel_launch(void* const* d_in, const int* in_sizes, int n_in,
                              void* d_out, int out_size) {
    const float* x   = (const float*)d_in[0];   // [4,32,256,256]
    const float* xf  = (const float*)d_in[1];   // [48,32,256,256]
    const float* sal = (const float*)d_in[2];   // [4,1,256,256]
    float*       out = (float*)d_out;           // [8,32,256,256]

    dim3 gridR(BPB, BZ);
    k_reduce<<<gridR, RTPB>>>(x, xf, sal);
    k_select<<<1, 192>>>();
    const unsigned blocksC = (unsigned)((2LL * BZ * CHW4) / (TPB * CPT)); // 2048
    k_copy<<<blocksC, TPB>>>(xf, out);
}

// round 12
// speedup vs baseline: 1.3721x; 1.0519x over previous
#include <cuda_runtime.h>

// Shapes fixed by the problem: bz=4, C=32, H=W=256, NF=12 focal slices.
#define NF    12
#define BZ    4
#define C_    32
#define HW    65536           // 256*256
#define CHW   (C_ * HW)       // 2,097,152
#define CHW4  (CHW / 4)       // 524,288 = 2^19
#define HW4   (HW / 4)        // 16,384

#define BPB   128             // reduction blocks along the chunk axis (R2-exact)
#define TPB   256
#define CHUNK (CHW4 / BPB)    // 4096 float4 per block (16 iters/thread)

// Scratch (no allocation allowed). Flags self-reset each launch.
__device__ float    g_part[BZ * NF * BPB];   // 24 KB -> L2-resident for k_copy
__device__ int      g_sel[2 * BZ];
__device__ unsigned g_ready = 0;             // selection-published flag
__device__ unsigned g_done  = 0;             // copy-finished counter (for reset)

// ---------------------------------------------------------------------------
// Kernel 1: EXACT R2 reduce (best measured: 68.7us @ 81% DRAM). Each block
// owns one (b, chunk), accumulates ALL 12 focal MAEs (14 independent 16B
// loads in flight per iteration). grid = (BPB, BZ).
// ---------------------------------------------------------------------------
__global__ __launch_bounds__(TPB, 2) void k_reduce(const float* __restrict__ x,
                                                   const float* __restrict__ xf,
                                                   const float* __restrict__ sal) {
    const int b    = blockIdx.y;
    const int base = blockIdx.x * CHUNK;

    const float4* __restrict__ xp = (const float4*)(x   + (size_t)b * CHW);
    const float4* __restrict__ sp = (const float4*)(sal + (size_t)b * HW);

    const float4* __restrict__ fp[NF];
#pragma unroll
    for (int f = 0; f < NF; ++f)
        fp[f] = (const float4*)(xf + ((size_t)f * BZ + b) * CHW);

    float acc[NF];
#pragma unroll
    for (int f = 0; f < NF; ++f) acc[f] = 0.f;

    for (int i = threadIdx.x; i < CHUNK; i += TPB) {
        const int v = base + i;
        const float4 a = xp[v];
        const float4 s = sp[v & (HW4 - 1)];       // sal broadcast over channels
        float4 g[NF];
#pragma unroll
        for (int f = 0; f < NF; ++f) g[f] = __ldcs(&fp[f][v]);
#pragma unroll
        for (int f = 0; f < NF; ++f) {
            acc[f] += fabsf(s.x * (a.x - g[f].x));
            acc[f] += fabsf(s.y * (a.y - g[f].y));
            acc[f] += fabsf(s.z * (a.z - g[f].z));
            acc[f] += fabsf(s.w * (a.w - g[f].w));
        }
    }

    const int lane = threadIdx.x & 31;
    const int warp = threadIdx.x >> 5;
#pragma unroll
    for (int f = 0; f < NF; ++f) {
        float v = acc[f];
#pragma unroll
        for (int o = 16; o > 0; o >>= 1)
            v += __shfl_down_sync(0xffffffffu, v, o);
        acc[f] = v;   // valid on lane 0
    }

    __shared__ float sh[TPB / 32][NF];
    if (lane == 0) {
#pragma unroll
        for (int f = 0; f < NF; ++f) sh[warp][f] = acc[f];
    }
    __syncthreads();
    if (threadIdx.x < NF) {
        const int f = threadIdx.x;
        float s = 0.f;
#pragma unroll
        for (int w = 0; w < TPB / 32; ++w) s += sh[w][f];
        g_part[(b * NF + f) * BPB + blockIdx.x] = s;
    }
}

// ---------------------------------------------------------------------------
// Kernel 2: gather-copy. Block 0 performs the selection (once) and publishes
// g_sel via a flag; all other blocks spin briefly. Then every block streams
// its 2048-float4 chunk (one output row per block). Last block resets flags.
// ---------------------------------------------------------------------------
#define CPT 8
__global__ __launch_bounds__(TPB) void k_copy(const float* __restrict__ xf,
                                              float* __restrict__ out) {
    const int t = threadIdx.x;

    if (blockIdx.x == 0) {
        // ---- selection: parallel partial sums, fixed-order combine ----
        __shared__ double sp16[BZ * NF][4];
        __shared__ double mae[BZ * NF];
        if (t < BZ * NF * 4) {                  // 192 threads
            const int bf = t >> 2;
            const int g  = t & 3;
            const float* __restrict__ row = &g_part[bf * BPB + g * 32];
            double s = 0.0;
#pragma unroll 8
            for (int q = 0; q < 32; ++q)        // batched -> MLP 8
                s += (double)__ldg(&row[q]);
            sp16[bf][g] = s;
        }
        __syncthreads();
        if (t < BZ * NF)
            mae[t] = ((sp16[t][0] + sp16[t][1]) + sp16[t][2]) + sp16[t][3];
        __syncthreads();
        if (t < BZ) {
            double m[NF];
#pragma unroll
            for (int f = 0; f < NF; ++f) m[f] = mae[t * NF + f];
            double best = -1.0;
            int bi = 0, bj = 0;
            for (int i = 0; i < NF; ++i)
                for (int j = i + 1; j < NF; ++j) {
                    const double d = m[i] - m[j];
                    const double v = d * d;      // 0.5 irrelevant for ordering
                    if (v > best) { best = v; bi = i; bj = j; }
                }
            if (!(best > 0.0)) { bi = 0; bj = 0; }
            g_sel[t]      = bi;
            g_sel[BZ + t] = bj;
        }
        __syncthreads();
        if (t == 0) {
            __threadfence();
            atomicExch(&g_ready, 1u);
        }
    } else {
        // ---- wait for selection ----
        if (t == 0) {
            while (atomicAdd(&g_ready, 0u) == 0u) __nanosleep(64);
        }
        __syncthreads();
        __threadfence();
    }

    // ---- streaming copy (R6-proven): batch 8 loads, then 8 stores ----
    const long long q0 = (long long)blockIdx.x * (TPB * CPT);
    const int r     = (int)(q0 >> 19);      // output row 0..7, constant per block
    const int b     = r & (BZ - 1);
    const int which = r >> 2;
    const int f     = g_sel[which * BZ + b];

    const float4* __restrict__ src = (const float4*)(xf + ((size_t)f * BZ + b) * CHW);
    float4* __restrict__ dst = (float4*)out;

    const int n0 = (int)(q0 & (CHW4 - 1)) + t;
    float4 v[CPT];
#pragma unroll
    for (int c = 0; c < CPT; ++c) v[c] = __ldcs(&src[n0 + c * TPB]);
#pragma unroll
    for (int c = 0; c < CPT; ++c) dst[q0 + t + c * TPB] = v[c];

    // ---- reset flags for next graph replay ----
    if (t == 0) {
        if (atomicAdd(&g_done, 1u) == gridDim.x - 1u) {
            g_ready = 0;
            g_done  = 0;
        }
    }
}

// ---------------------------------------------------------------------------
extern "C" void kernel_launch(void* const* d_in, const int* in_sizes, int n_in,
                              void* d_out, int out_size) {
    const float* x   = (const float*)d_in[0];   // [4,32,256,256]
    const float* xf  = (const float*)d_in[1];   // [48,32,256,256]
    const float* sal = (const float*)d_in[2];   // [4,1,256,256]
    float*       out = (float*)d_out;           // [8,32,256,256]

    dim3 gridR(BPB, BZ);
    k_reduce<<<gridR, TPB>>>(x, xf, sal);
    const unsigned blocksC = (unsigned)((2LL * BZ * CHW4) / (TPB * CPT)); // 2048
    k_copy<<<blocksC, TPB>>>(xf, out);
}

// round 13
// speedup vs baseline: 1.4046x; 1.0237x over previous
#include <cuda_runtime.h>

// Shapes fixed by the problem: bz=4, C=32, H=W=256, NF=12 focal slices.
#define NF    12
#define BZ    4
#define C_    32
#define HW    65536           // 256*256
#define CHW   (C_ * HW)       // 2,097,152
#define CHW4  (CHW / 4)       // 524,288 = 2^19
#define HW4   (HW / 4)        // 16,384

#define BPB   128             // reduction blocks along the chunk axis (R2-exact)
#define TPB   256
#define CHUNK (CHW4 / BPB)    // 4096 float4 per block (16 iters/thread)

// Scratch (no allocation allowed).
__device__ float g_part[BZ * NF * BPB];   // 24 KB -> L2-resident for k_select
__device__ int   g_sel[2 * BZ];           // [0..BZ) = i, [BZ..2BZ) = j per batch

// ---------------------------------------------------------------------------
// Kernel 1: EXACT R2 reduce (best measured: 68.7us @ 81% DRAM, 86 regs).
// Each block owns one (b, chunk), accumulates ALL 12 focal MAEs
// (14 independent 16B loads in flight per iteration). grid = (BPB, BZ).
// ---------------------------------------------------------------------------
__global__ __launch_bounds__(TPB, 2) void k_reduce(const float* __restrict__ x,
                                                   const float* __restrict__ xf,
                                                   const float* __restrict__ sal) {
    const int b    = blockIdx.y;
    const int base = blockIdx.x * CHUNK;

    const float4* __restrict__ xp = (const float4*)(x   + (size_t)b * CHW);
    const float4* __restrict__ sp = (const float4*)(sal + (size_t)b * HW);

    const float4* __restrict__ fp[NF];
#pragma unroll
    for (int f = 0; f < NF; ++f)
        fp[f] = (const float4*)(xf + ((size_t)f * BZ + b) * CHW);

    float acc[NF];
#pragma unroll
    for (int f = 0; f < NF; ++f) acc[f] = 0.f;

    for (int i = threadIdx.x; i < CHUNK; i += TPB) {
        const int v = base + i;
        const float4 a = xp[v];
        const float4 s = sp[v & (HW4 - 1)];       // sal broadcast over channels
        float4 g[NF];
#pragma unroll
        for (int f = 0; f < NF; ++f) g[f] = __ldcs(&fp[f][v]);
#pragma unroll
        for (int f = 0; f < NF; ++f) {
            acc[f] += fabsf(s.x * (a.x - g[f].x));
            acc[f] += fabsf(s.y * (a.y - g[f].y));
            acc[f] += fabsf(s.z * (a.z - g[f].z));
            acc[f] += fabsf(s.w * (a.w - g[f].w));
        }
    }

    // Warp shuffle reduce each of the 12 accumulators, then combine warps.
    const int lane = threadIdx.x & 31;
    const int warp = threadIdx.x >> 5;
#pragma unroll
    for (int f = 0; f < NF; ++f) {
        float v = acc[f];
#pragma unroll
        for (int o = 16; o > 0; o >>= 1)
            v += __shfl_down_sync(0xffffffffu, v, o);
        acc[f] = v;   // valid on lane 0
    }

    __shared__ float sh[TPB / 32][NF];
    if (lane == 0) {
#pragma unroll
        for (int f = 0; f < NF; ++f) sh[warp][f] = acc[f];
    }
    __syncthreads();
    if (threadIdx.x < NF) {
        const int f = threadIdx.x;
        float s = 0.f;
#pragma unroll
        for (int w = 0; w < TPB / 32; ++w) s += sh[w][f];
        g_part[(b * NF + f) * BPB + blockIdx.x] = s;
    }
}

// ---------------------------------------------------------------------------
// Kernel 2: tiny standalone selection. 192 threads: 4 partial-summers per
// (b,f) with batched independent loads, fixed-order double combine
// (deterministic), then per-batch 66-pair first-max with strict '>'.
// ---------------------------------------------------------------------------
__global__ void k_select() {
    __shared__ double part4[BZ * NF][4];
    __shared__ double mae[BZ * NF];
    const int t = threadIdx.x;

    if (t < BZ * NF * 4) {
        const int bf = t >> 2;
        const int g  = t & 3;
        const float* __restrict__ row = &g_part[bf * BPB + g * 32];
        double s = 0.0;
#pragma unroll 8
        for (int q = 0; q < 32; ++q)             // batched -> MLP 8
            s += (double)__ldg(&row[q]);
        part4[bf][g] = s;
    }
    __syncthreads();
    if (t < BZ * NF)
        mae[t] = ((part4[t][0] + part4[t][1]) + part4[t][2]) + part4[t][3];
    __syncthreads();
    if (t < BZ) {
        double m[NF];
#pragma unroll
        for (int f = 0; f < NF; ++f) m[f] = mae[t * NF + f];
        double best = -1.0;
        int bi = 0, bj = 0;
        for (int i = 0; i < NF; ++i)
            for (int j = i + 1; j < NF; ++j) {
                const double d = m[i] - m[j];
                const double v = d * d;          // 0.5 irrelevant for ordering
                if (v > best) { best = v; bi = i; bj = j; }
            }
        if (!(best > 0.0)) { bi = 0; bj = 0; }
        g_sel[t]      = bi;
        g_sel[BZ + t] = bj;
    }
}

// ---------------------------------------------------------------------------
// Kernel 3: EXACT R6 gather-copy (best measured: 18.6us = 6.9 TB/s effective).
// Batch 8 streaming loads into registers, then 8 write-back stores.
// Block chunk = 2048 float4, divides CHW4 -> one output row per block.
// ---------------------------------------------------------------------------
#define CPT 8
__global__ __launch_bounds__(TPB) void k_copy(const float* __restrict__ xf,
                                              float* __restrict__ out) {
    const long long q0 = (long long)blockIdx.x * (TPB * CPT);
    const int r     = (int)(q0 >> 19);      // output row 0..7, constant per block
    const int b     = r & (BZ - 1);
    const int which = r >> 2;
    const int f     = g_sel[which * BZ + b];

    const float4* __restrict__ src = (const float4*)(xf + ((size_t)f * BZ + b) * CHW);
    float4* __restrict__ dst = (float4*)out;

    const int n0 = (int)(q0 & (CHW4 - 1)) + threadIdx.x;
    float4 v[CPT];
#pragma unroll
    for (int c = 0; c < CPT; ++c) v[c] = __ldcs(&src[n0 + c * TPB]);
#pragma unroll
    for (int c = 0; c < CPT; ++c) dst[q0 + threadIdx.x + c * TPB] = v[c];
}

// ---------------------------------------------------------------------------
extern "C" void kernel_launch(void* const* d_in, const int* in_sizes, int n_in,
                              void* d_out, int out_size) {
    const float* x   = (const float*)d_in[0];   // [4,32,256,256]
    const float* xf  = (const float*)d_in[1];   // [48,32,256,256]
    const float* sal = (const float*)d_in[2];   // [4,1,256,256]
    float*       out = (float*)d_out;           // [8,32,256,256]

    dim3 gridR(BPB, BZ);
    k_reduce<<<gridR, TPB>>>(x, xf, sal);
    k_select<<<1, 192>>>();
    const unsigned blocksC = (unsigned)((2LL * BZ * CHW4) / (TPB * CPT)); // 2048
    k_copy<<<blocksC, TPB>>>(xf, out);
}

// round 15
// speedup vs baseline: 1.4239x; 1.0137x over previous
#include <cuda_runtime.h>

// Shapes fixed by the problem: bz=4, C=32, H=W=256, NF=12 focal slices.
#define NF    12
#define BZ    4
#define C_    32
#define HW    65536           // 256*256
#define CHW   (C_ * HW)       // 2,097,152
#define CHW4  (CHW / 4)       // 524,288 = 2^19
#define HW4   (HW / 4)        // 16,384

#define BPB   128             // reduction blocks along the chunk axis (R2-exact)
#define TPB   256
#define CHUNK (CHW4 / BPB)    // 4096 float4 per block (16 iters/thread)

// Scratch (no allocation allowed).
__device__ float g_part[BZ * NF * BPB];   // 24 KB -> L2-resident for k_select
__device__ int   g_sel[2 * BZ];           // [0..BZ) = i, [BZ..2BZ) = j per batch

// ---------------------------------------------------------------------------
// Kernel 1: EXACT R2 reduce (best measured: 68.7us @ 81% DRAM, 86 regs).
// Each block owns one (b, chunk), accumulates ALL 12 focal MAEs
// (14 independent 16B loads in flight per iteration). grid = (BPB, BZ).
// ---------------------------------------------------------------------------
__global__ __launch_bounds__(TPB, 2) void k_reduce(const float* __restrict__ x,
                                                   const float* __restrict__ xf,
                                                   const float* __restrict__ sal) {
    const int b    = blockIdx.y;
    const int base = blockIdx.x * CHUNK;

    const float4* __restrict__ xp = (const float4*)(x   + (size_t)b * CHW);
    const float4* __restrict__ sp = (const float4*)(sal + (size_t)b * HW);

    const float4* __restrict__ fp[NF];
#pragma unroll
    for (int f = 0; f < NF; ++f)
        fp[f] = (const float4*)(xf + ((size_t)f * BZ + b) * CHW);

    float acc[NF];
#pragma unroll
    for (int f = 0; f < NF; ++f) acc[f] = 0.f;

    for (int i = threadIdx.x; i < CHUNK; i += TPB) {
        const int v = base + i;
        const float4 a = xp[v];
        const float4 s = sp[v & (HW4 - 1)];       // sal broadcast over channels
        float4 g[NF];
#pragma unroll
        for (int f = 0; f < NF; ++f) g[f] = __ldcs(&fp[f][v]);
#pragma unroll
        for (int f = 0; f < NF; ++f) {
            acc[f] += fabsf(s.x * (a.x - g[f].x));
            acc[f] += fabsf(s.y * (a.y - g[f].y));
            acc[f] += fabsf(s.z * (a.z - g[f].z));
            acc[f] += fabsf(s.w * (a.w - g[f].w));
        }
    }

    // Warp shuffle reduce each of the 12 accumulators, then combine warps.
    const int lane = threadIdx.x & 31;
    const int warp = threadIdx.x >> 5;
#pragma unroll
    for (int f = 0; f < NF; ++f) {
        float v = acc[f];
#pragma unroll
        for (int o = 16; o > 0; o >>= 1)
            v += __shfl_down_sync(0xffffffffu, v, o);
        acc[f] = v;   // valid on lane 0
    }

    __shared__ float sh[TPB / 32][NF];
    if (lane == 0) {
#pragma unroll
        for (int f = 0; f < NF; ++f) sh[warp][f] = acc[f];
    }
    __syncthreads();
    if (threadIdx.x < NF) {
        const int f = threadIdx.x;
        float s = 0.f;
#pragma unroll
        for (int w = 0; w < TPB / 32; ++w) s += sh[w][f];
        g_part[(b * NF + f) * BPB + blockIdx.x] = s;
    }
}

// ---------------------------------------------------------------------------
// Kernel 2: tiny standalone selection. PDL-gated on k_reduce's output.
// ---------------------------------------------------------------------------
__global__ void k_select() {
#if __CUDA_ARCH__ >= 900
    cudaGridDependencySynchronize();   // wait for k_reduce's g_part writes
#endif
    __shared__ double part4[BZ * NF][4];
    __shared__ double mae[BZ * NF];
    const int t = threadIdx.x;

    if (t < BZ * NF * 4) {
        const int bf = t >> 2;
        const int g  = t & 3;
        const float* __restrict__ row = &g_part[bf * BPB + g * 32];
        double s = 0.0;
#pragma unroll 8
        for (int q = 0; q < 32; ++q)             // batched -> MLP 8
            s += (double)__ldg(&row[q]);
        part4[bf][g] = s;
    }
    __syncthreads();
    if (t < BZ * NF)
        mae[t] = ((part4[t][0] + part4[t][1]) + part4[t][2]) + part4[t][3];
    __syncthreads();
    if (t < BZ) {
        double m[NF];
#pragma unroll
        for (int f = 0; f < NF; ++f) m[f] = mae[t * NF + f];
        double best = -1.0;
        int bi = 0, bj = 0;
        for (int i = 0; i < NF; ++i)
            for (int j = i + 1; j < NF; ++j) {
                const double d = m[i] - m[j];
                const double v = d * d;          // 0.5 irrelevant for ordering
                if (v > best) { best = v; bi = i; bj = j; }
            }
        if (!(best > 0.0)) { bi = 0; bj = 0; }
        g_sel[t]      = bi;
        g_sel[BZ + t] = bj;
    }
}

// ---------------------------------------------------------------------------
// Kernel 3: EXACT R6 gather-copy (best measured: 18.6us). PDL-gated on g_sel.
// Batch 8 streaming loads into registers, then 8 write-back stores.
// Block chunk = 2048 float4, divides CHW4 -> one output row per block.
// ---------------------------------------------------------------------------
#define CPT 8
__global__ __launch_bounds__(TPB) void k_copy(const float* __restrict__ xf,
                                              float* __restrict__ out) {
    const long long q0 = (long long)blockIdx.x * (TPB * CPT);
    const int r     = (int)(q0 >> 19);      // output row 0..7, constant per block
    const int b     = r & (BZ - 1);
    const int which = r >> 2;

#if __CUDA_ARCH__ >= 900
    cudaGridDependencySynchronize();   // wait for k_select's g_sel writes
#endif
    const int f = g_sel[which * BZ + b];

    const float4* __restrict__ src = (const float4*)(xf + ((size_t)f * BZ + b) * CHW);
    float4* __restrict__ dst = (float4*)out;

    const int n0 = (int)(q0 & (CHW4 - 1)) + threadIdx.x;
    float4 v[CPT];
#pragma unroll
    for (int c = 0; c < CPT; ++c) v[c] = __ldcs(&src[n0 + c * TPB]);
#pragma unroll
    for (int c = 0; c < CPT; ++c) dst[q0 + threadIdx.x + c * TPB] = v[c];
}

// ---------------------------------------------------------------------------
// Launch: three kernels; select and copy use Programmatic Dependent Launch so
// their launch latency overlaps the predecessor's execution (gap removal).
// ---------------------------------------------------------------------------
static void launch_pdl(const void* func, dim3 grid, dim3 block,
                       void** args) {
    cudaLaunchConfig_t cfg = {};
    cfg.gridDim  = grid;
    cfg.blockDim = block;
    cfg.dynamicSmemBytes = 0;
    cfg.stream = 0;
    cudaLaunchAttribute attr[1];
    attr[0].id = cudaLaunchAttributeProgrammaticStreamSerialization;
    attr[0].val.programmaticStreamSerializationAllowed = 1;
    cfg.attrs = attr;
    cfg.numAttrs = 1;
    cudaLaunchKernelExC(&cfg, func, args);
}

extern "C" void kernel_launch(void* const* d_in, const int* in_sizes, int n_in,
                              void* d_out, int out_size) {
    const float* x   = (const float*)d_in[0];   // [4,32,256,256]
    const float* xf  = (const float*)d_in[1];   // [48,32,256,256]
    const float* sal = (const float*)d_in[2];   // [4,1,256,256]
    float*       out = (float*)d_out;           // [8,32,256,256]

    dim3 gridR(BPB, BZ);
    k_reduce<<<gridR, TPB>>>(x, xf, sal);

    {   // k_select with PDL on k_reduce
        void* args[] = {};
        launch_pdl((const void*)k_select, dim3(1), dim3(192), args);
    }
    {   // k_copy with PDL on k_select
        const unsigned blocksC = (unsigned)((2LL * BZ * CHW4) / (TPB * CPT)); // 2048
        void* a0 = (void*)xf; void* a1 = (void*)out;
        void* args[] = {&a0, &a1};
        launch_pdl((const void*)k_copy, dim3(blocksC), dim3(TPB), args);
    }
}